// round 1
// baseline (speedup 1.0000x reference)
#include <cuda_runtime.h>
#include <cstdint>

// Problem constants (fixed by the dataset)
#define BATCH 32768
#define TSTEPS 60
#define FIN 26
#define HID 24
#define G3 (3 * HID)   // 72

typedef unsigned long long u64;

// ---------- packed f32x2 helpers ----------
__device__ __forceinline__ u64 pk(float a, float b) {
    u64 r;
    asm("mov.b64 %0, {%1, %2};" : "=l"(r) : "f"(a), "f"(b));
    return r;
}
__device__ __forceinline__ void upk(u64 v, float& a, float& b) {
    asm("mov.b64 {%0, %1}, %2;" : "=f"(a), "=f"(b) : "l"(v));
}
__device__ __forceinline__ u64 ffma2(u64 a, u64 b, u64 c) {
    u64 d;
    asm("fma.rn.f32x2 %0, %1, %2, %3;" : "=l"(d) : "l"(a), "l"(b), "l"(c));
    return d;
}

// ---------- fast, accurate-enough activations (≈1e-6 rel err) ----------
__device__ __forceinline__ float sigmoidf_(float x) {
    return __fdividef(1.0f, 1.0f + __expf(-x));
}
__device__ __forceinline__ float tanhf_(float x) {
    // tanh(x) = 2*sigmoid(2x) - 1
    float s = __fdividef(2.0f, 1.0f + __expf(-2.0f * x));
    return s - 1.0f;
}

__global__ void __launch_bounds__(128, 1)
_ShotRNN_90417651516362_kernel(
    const float* __restrict__ x,      // [B, T, 26]
    const float* __restrict__ w_ih,   // [72, 26]
    const float* __restrict__ w_hh,   // [72, 24]
    const float* __restrict__ b_ih,   // [72]
    const float* __restrict__ b_hh,   // [72]
    const float* __restrict__ fc1_w,  // [8, 24]
    const float* __restrict__ fc1_b,  // [8]
    const float* __restrict__ fc2_w,  // [4, 8]
    const float* __restrict__ fc2_b,  // [4]
    float* __restrict__ out)          // [B, 4]
{
    // Duplicated-pair weights in SMEM: each scalar stored as (w, w) in 8 bytes
    __shared__ u64 s_wih[G3 * FIN];   // 72*26
    __shared__ u64 s_whh[G3 * HID];   // 72*24
    __shared__ u64 s_br[HID];         // b_ih[r]+b_hh[r]
    __shared__ u64 s_bz[HID];         // b_ih[z]+b_hh[z]
    __shared__ u64 s_bnx[HID];        // b_ih[n]
    __shared__ u64 s_bnh[HID];        // b_hh[n]
    __shared__ u64 s_f1w[8 * HID];
    __shared__ u64 s_f1b[8];
    __shared__ u64 s_f2w[4 * 8];
    __shared__ u64 s_f2b[4];

    const int tid = threadIdx.x;
    const int blk = blockDim.x;

    for (int i = tid; i < G3 * FIN; i += blk) { float w = w_ih[i]; s_wih[i] = pk(w, w); }
    for (int i = tid; i < G3 * HID; i += blk) { float w = w_hh[i]; s_whh[i] = pk(w, w); }
    for (int i = tid; i < HID; i += blk) {
        float br = b_ih[i]        + b_hh[i];        s_br[i]  = pk(br, br);
        float bz = b_ih[HID + i]  + b_hh[HID + i];  s_bz[i]  = pk(bz, bz);
        float bx = b_ih[2*HID + i];                 s_bnx[i] = pk(bx, bx);
        float bh = b_hh[2*HID + i];                 s_bnh[i] = pk(bh, bh);
    }
    for (int i = tid; i < 8 * HID; i += blk) { float w = fc1_w[i]; s_f1w[i] = pk(w, w); }
    for (int i = tid; i < 8; i += blk)       { float w = fc1_b[i]; s_f1b[i] = pk(w, w); }
    for (int i = tid; i < 32; i += blk)      { float w = fc2_w[i]; s_f2w[i] = pk(w, w); }
    for (int i = tid; i < 4; i += blk)       { float w = fc2_b[i]; s_f2b[i] = pk(w, w); }
    __syncthreads();

    const int gid = blockIdx.x * blk + tid;
    const int b0 = 2 * gid;
    if (b0 + 1 >= BATCH + 1) return;  // exact fit; guard is vestigial

    const float* xr0 = x + (size_t)b0 * (TSTEPS * FIN);
    const float* xr1 = xr0 + (TSTEPS * FIN);

    u64 h[HID];
#pragma unroll
    for (int i = 0; i < HID; i++) h[i] = 0ull;

#pragma unroll 1
    for (int t = 0; t < TSTEPS; t++) {
        // Load the two x rows (26 floats each; rows are 8B-aligned -> float2)
        float a0[FIN], a1[FIN];
        const float2* p0 = (const float2*)(xr0 + t * FIN);
        const float2* p1 = (const float2*)(xr1 + t * FIN);
#pragma unroll
        for (int f = 0; f < FIN / 2; f++) {
            float2 v0 = __ldg(p0 + f);
            float2 v1 = __ldg(p1 + f);
            a0[2*f] = v0.x; a0[2*f+1] = v0.y;
            a1[2*f] = v1.x; a1[2*f+1] = v1.y;
        }
        u64 xp[FIN];
#pragma unroll
        for (int f = 0; f < FIN; f++) xp[f] = pk(a0[f], a1[f]);

        u64 hn[HID];
#pragma unroll 2
        for (int i = 0; i < HID; i++) {
            u64 ar  = s_br[i];
            u64 az  = s_bz[i];
            u64 anx = s_bnx[i];
            u64 anh = s_bnh[i];

            const u64* wr = &s_wih[i * FIN];
            const u64* wz = &s_wih[(HID + i) * FIN];
            const u64* wn = &s_wih[(2 * HID + i) * FIN];
#pragma unroll
            for (int f = 0; f < FIN; f++) {
                ar  = ffma2(xp[f], wr[f], ar);
                az  = ffma2(xp[f], wz[f], az);
                anx = ffma2(xp[f], wn[f], anx);
            }

            const u64* ur = &s_whh[i * HID];
            const u64* uz = &s_whh[(HID + i) * HID];
            const u64* un = &s_whh[(2 * HID + i) * HID];
#pragma unroll
            for (int j = 0; j < HID; j++) {
                ar  = ffma2(h[j], ur[j], ar);
                az  = ffma2(h[j], uz[j], az);
                anh = ffma2(h[j], un[j], anh);
            }

            float arx, ary, azx, azy, nxx, nxy, nhx, nhy, h0, h1v;
            upk(ar, arx, ary);
            upk(az, azx, azy);
            upk(anx, nxx, nxy);
            upk(anh, nhx, nhy);
            upk(h[i], h0, h1v);

            float r0 = sigmoidf_(arx), r1 = sigmoidf_(ary);
            float z0 = sigmoidf_(azx), z1 = sigmoidf_(azy);
            float n0 = tanhf_(fmaf(r0, nhx, nxx));
            float n1 = tanhf_(fmaf(r1, nhy, nxy));
            // h_new = (1-z)*n + z*h = n + z*(h - n)
            float o0 = fmaf(z0, h0 - n0, n0);
            float o1 = fmaf(z1, h1v - n1, n1);
            hn[i] = pk(o0, o1);
        }
#pragma unroll
        for (int i = 0; i < HID; i++) h[i] = hn[i];
    }

    // ---- FC1 (24->8) + ReLU ----
    u64 h1[8];
#pragma unroll
    for (int j = 0; j < 8; j++) {
        u64 acc = s_f1b[j];
        const u64* w = &s_f1w[j * HID];
#pragma unroll
        for (int k = 0; k < HID; k++) acc = ffma2(h[k], w[k], acc);
        float a, b;
        upk(acc, a, b);
        a = fmaxf(a, 0.0f);
        b = fmaxf(b, 0.0f);
        h1[j] = pk(a, b);
    }

    // ---- FC2 (8->4) ----
    float l0[4], l1[4];
#pragma unroll
    for (int c = 0; c < 4; c++) {
        u64 acc = s_f2b[c];
        const u64* w = &s_f2w[c * 8];
#pragma unroll
        for (int k = 0; k < 8; k++) acc = ffma2(h1[k], w[k], acc);
        upk(acc, l0[c], l1[c]);
    }

    // ---- softmax over 4, per batch element ----
    float* o0p = out + (size_t)b0 * 4;
    float* o1p = o0p + 4;
    {
        float m = fmaxf(fmaxf(l0[0], l0[1]), fmaxf(l0[2], l0[3]));
        float e[4]; float s = 0.0f;
#pragma unroll
        for (int c = 0; c < 4; c++) { e[c] = __expf(l0[c] - m); s += e[c]; }
        float inv = __fdividef(1.0f, s);
#pragma unroll
        for (int c = 0; c < 4; c++) o0p[c] = e[c] * inv;
    }
    {
        float m = fmaxf(fmaxf(l1[0], l1[1]), fmaxf(l1[2], l1[3]));
        float e[4]; float s = 0.0f;
#pragma unroll
        for (int c = 0; c < 4; c++) { e[c] = __expf(l1[c] - m); s += e[c]; }
        float inv = __fdividef(1.0f, s);
#pragma unroll
        for (int c = 0; c < 4; c++) o1p[c] = e[c] * inv;
    }
}

extern "C" void kernel_launch(void* const* d_in, const int* in_sizes, int n_in,
                              void* d_out, int out_size) {
    const float* x     = (const float*)d_in[0];
    const float* w_ih  = (const float*)d_in[1];
    const float* w_hh  = (const float*)d_in[2];
    const float* b_ih  = (const float*)d_in[3];
    const float* b_hh  = (const float*)d_in[4];
    const float* fc1_w = (const float*)d_in[5];
    const float* fc1_b = (const float*)d_in[6];
    const float* fc2_w = (const float*)d_in[7];
    const float* fc2_b = (const float*)d_in[8];
    float* out = (float*)d_out;

    // 16384 threads, 2 batch elements each (f32x2-packed)
    dim3 grid(128), block(128);
    _ShotRNN_90417651516362_kernel<<<grid, block>>>(
        x, w_ih, w_hh, b_ih, b_hh, fc1_w, fc1_b, fc2_w, fc2_b, out);
}

// round 2
// speedup vs baseline: 1.0625x; 1.0625x over previous
#include <cuda_runtime.h>
#include <cstdint>

#define BATCH 32768
#define TSTEPS 60
#define FIN 26
#define HID 24
#define G3 (3 * HID)   // 72

typedef unsigned long long u64;

// ---------- packed f32x2 helpers ----------
__device__ __forceinline__ u64 pk(float a, float b) {
    u64 r;
    asm("mov.b64 %0, {%1, %2};" : "=l"(r) : "f"(a), "f"(b));
    return r;
}
__device__ __forceinline__ void upk(u64 v, float& a, float& b) {
    asm("mov.b64 {%0, %1}, %2;" : "=f"(a), "=f"(b) : "l"(v));
}
// In-place accumulate: dst register IS the addend -> no pair copies
__device__ __forceinline__ void ffma2_ip(u64& acc, u64 a, u64 b) {
    asm("fma.rn.f32x2 %0, %1, %2, %0;" : "+l"(acc) : "l"(a), "l"(b));
}

// ---------- fast, accurate-enough activations ----------
__device__ __forceinline__ float sigmoidf_(float x) {
    return __fdividef(1.0f, 1.0f + __expf(-x));
}
__device__ __forceinline__ float tanhf_(float x) {
    float s = __fdividef(2.0f, 1.0f + __expf(-2.0f * x));
    return s - 1.0f;
}

__global__ void __launch_bounds__(128, 1)
_ShotRNN_90417651516362_kernel(
    const float* __restrict__ x,      // [B, T, 26]
    const float* __restrict__ w_ih,   // [72, 26]
    const float* __restrict__ w_hh,   // [72, 24]
    const float* __restrict__ b_ih,   // [72]
    const float* __restrict__ b_hh,   // [72]
    const float* __restrict__ fc1_w,  // [8, 24]
    const float* __restrict__ fc1_b,  // [8]
    const float* __restrict__ fc2_w,  // [4, 8]
    const float* __restrict__ fc2_b,  // [4]
    float* __restrict__ out)          // [B, 4]
{
    // Duplicated-pair weights in SMEM (each scalar stored as (w,w) u64).
    // 16B-aligned so ulonglong2 (LDS.128) loads are legal. Row sizes:
    // wih row = 26*8 = 208B (16|208 OK), whh row = 24*8 = 192B (16|192 OK).
    __shared__ __align__(16) u64 s_wih[G3 * FIN];
    __shared__ __align__(16) u64 s_whh[G3 * HID];
    __shared__ __align__(16) u64 s_br[HID];
    __shared__ __align__(16) u64 s_bz[HID];
    __shared__ __align__(16) u64 s_bnx[HID];
    __shared__ __align__(16) u64 s_bnh[HID];
    __shared__ __align__(16) u64 s_f1w[8 * HID];
    __shared__ __align__(16) u64 s_f1b[8];
    __shared__ __align__(16) u64 s_f2w[4 * 8];
    __shared__ __align__(16) u64 s_f2b[4];

    const int tid = threadIdx.x;
    const int blk = blockDim.x;

    for (int i = tid; i < G3 * FIN; i += blk) { float w = w_ih[i]; s_wih[i] = pk(w, w); }
    for (int i = tid; i < G3 * HID; i += blk) { float w = w_hh[i]; s_whh[i] = pk(w, w); }
    for (int i = tid; i < HID; i += blk) {
        float br = b_ih[i]        + b_hh[i];        s_br[i]  = pk(br, br);
        float bz = b_ih[HID + i]  + b_hh[HID + i];  s_bz[i]  = pk(bz, bz);
        float bx = b_ih[2*HID + i];                 s_bnx[i] = pk(bx, bx);
        float bh = b_hh[2*HID + i];                 s_bnh[i] = pk(bh, bh);
    }
    for (int i = tid; i < 8 * HID; i += blk) { float w = fc1_w[i]; s_f1w[i] = pk(w, w); }
    for (int i = tid; i < 8; i += blk)       { float w = fc1_b[i]; s_f1b[i] = pk(w, w); }
    for (int i = tid; i < 32; i += blk)      { float w = fc2_w[i]; s_f2w[i] = pk(w, w); }
    for (int i = tid; i < 4; i += blk)       { float w = fc2_b[i]; s_f2b[i] = pk(w, w); }
    __syncthreads();

    const int gid = blockIdx.x * blk + tid;
    const int b0 = 2 * gid;

    const float* xr0 = x + (size_t)b0 * (TSTEPS * FIN);
    const float* xr1 = xr0 + (TSTEPS * FIN);

    u64 h[HID];
#pragma unroll
    for (int i = 0; i < HID; i++) h[i] = 0ull;

#pragma unroll 1
    for (int t = 0; t < TSTEPS; t++) {
        // ---- issue x loads for this step up front (float2, rows 8B-aligned) ----
        float2 v0[FIN / 2], v1[FIN / 2];
        const float2* p0 = (const float2*)(xr0 + t * FIN);
        const float2* p1 = (const float2*)(xr1 + t * FIN);
#pragma unroll
        for (int f = 0; f < FIN / 2; f++) {
            v0[f] = __ldg(p0 + f);
            v1[f] = __ldg(p1 + f);
        }
        u64 xp[FIN];
#pragma unroll
        for (int f = 0; f < FIN / 2; f++) {
            xp[2*f]   = pk(v0[f].x, v1[f].x);
            xp[2*f+1] = pk(v0[f].y, v1[f].y);
        }

        u64 hn[HID];
#pragma unroll 2
        for (int i = 0; i < HID; i++) {
            u64 ar  = s_br[i];
            u64 az  = s_bz[i];
            u64 anx = s_bnx[i];
            u64 anh = s_bnh[i];

            // ---- h-part first (SMEM + regs only; overlaps x LDG latency) ----
            const ulonglong2* ur = (const ulonglong2*)&s_whh[i * HID];
            const ulonglong2* uz = (const ulonglong2*)&s_whh[(HID + i) * HID];
            const ulonglong2* un = (const ulonglong2*)&s_whh[(2 * HID + i) * HID];
#pragma unroll
            for (int j = 0; j < HID / 2; j++) {
                ulonglong2 a = ur[j], b = uz[j], c = un[j];
                ffma2_ip(ar,  h[2*j],   a.x);
                ffma2_ip(az,  h[2*j],   b.x);
                ffma2_ip(anh, h[2*j],   c.x);
                ffma2_ip(ar,  h[2*j+1], a.y);
                ffma2_ip(az,  h[2*j+1], b.y);
                ffma2_ip(anh, h[2*j+1], c.y);
            }

            // ---- x-part (LDS.128 weight loads: 2 packed weights per load) ----
            const ulonglong2* wr = (const ulonglong2*)&s_wih[i * FIN];
            const ulonglong2* wz = (const ulonglong2*)&s_wih[(HID + i) * FIN];
            const ulonglong2* wn = (const ulonglong2*)&s_wih[(2 * HID + i) * FIN];
#pragma unroll
            for (int f = 0; f < FIN / 2; f++) {
                ulonglong2 a = wr[f], b = wz[f], c = wn[f];
                ffma2_ip(ar,  xp[2*f],   a.x);
                ffma2_ip(az,  xp[2*f],   b.x);
                ffma2_ip(anx, xp[2*f],   c.x);
                ffma2_ip(ar,  xp[2*f+1], a.y);
                ffma2_ip(az,  xp[2*f+1], b.y);
                ffma2_ip(anx, xp[2*f+1], c.y);
            }

            float arx, ary, azx, azy, nxx, nxy, nhx, nhy, h0, h1v;
            upk(ar, arx, ary);
            upk(az, azx, azy);
            upk(anx, nxx, nxy);
            upk(anh, nhx, nhy);
            upk(h[i], h0, h1v);

            float r0 = sigmoidf_(arx), r1 = sigmoidf_(ary);
            float z0 = sigmoidf_(azx), z1 = sigmoidf_(azy);
            float n0 = tanhf_(fmaf(r0, nhx, nxx));
            float n1 = tanhf_(fmaf(r1, nhy, nxy));
            float o0 = fmaf(z0, h0 - n0, n0);
            float o1 = fmaf(z1, h1v - n1, n1);
            hn[i] = pk(o0, o1);
        }
#pragma unroll
        for (int i = 0; i < HID; i++) h[i] = hn[i];
    }

    // ---- FC1 (24->8) + ReLU ----
    u64 h1[8];
#pragma unroll
    for (int j = 0; j < 8; j++) {
        u64 acc = s_f1b[j];
        const ulonglong2* w = (const ulonglong2*)&s_f1w[j * HID];
#pragma unroll
        for (int k = 0; k < HID / 2; k++) {
            ulonglong2 a = w[k];
            ffma2_ip(acc, h[2*k],   a.x);
            ffma2_ip(acc, h[2*k+1], a.y);
        }
        float a, b;
        upk(acc, a, b);
        h1[j] = pk(fmaxf(a, 0.0f), fmaxf(b, 0.0f));
    }

    // ---- FC2 (8->4) ----
    float l0[4], l1[4];
#pragma unroll
    for (int c = 0; c < 4; c++) {
        u64 acc = s_f2b[c];
        const ulonglong2* w = (const ulonglong2*)&s_f2w[c * 8];
#pragma unroll
        for (int k = 0; k < 4; k++) {
            ulonglong2 a = w[k];
            ffma2_ip(acc, h1[2*k],   a.x);
            ffma2_ip(acc, h1[2*k+1], a.y);
        }
        upk(acc, l0[c], l1[c]);
    }

    // ---- softmax over 4, per batch element ----
    float* o0p = out + (size_t)b0 * 4;
    float* o1p = o0p + 4;
    {
        float m = fmaxf(fmaxf(l0[0], l0[1]), fmaxf(l0[2], l0[3]));
        float e[4]; float s = 0.0f;
#pragma unroll
        for (int c = 0; c < 4; c++) { e[c] = __expf(l0[c] - m); s += e[c]; }
        float inv = __fdividef(1.0f, s);
#pragma unroll
        for (int c = 0; c < 4; c++) o0p[c] = e[c] * inv;
    }
    {
        float m = fmaxf(fmaxf(l1[0], l1[1]), fmaxf(l1[2], l1[3]));
        float e[4]; float s = 0.0f;
#pragma unroll
        for (int c = 0; c < 4; c++) { e[c] = __expf(l1[c] - m); s += e[c]; }
        float inv = __fdividef(1.0f, s);
#pragma unroll
        for (int c = 0; c < 4; c++) o1p[c] = e[c] * inv;
    }
}

extern "C" void kernel_launch(void* const* d_in, const int* in_sizes, int n_in,
                              void* d_out, int out_size) {
    const float* x     = (const float*)d_in[0];
    const float* w_ih  = (const float*)d_in[1];
    const float* w_hh  = (const float*)d_in[2];
    const float* b_ih  = (const float*)d_in[3];
    const float* b_hh  = (const float*)d_in[4];
    const float* fc1_w = (const float*)d_in[5];
    const float* fc1_b = (const float*)d_in[6];
    const float* fc2_w = (const float*)d_in[7];
    const float* fc2_b = (const float*)d_in[8];
    float* out = (float*)d_out;

    dim3 grid(128), block(128);
    _ShotRNN_90417651516362_kernel<<<grid, block>>>(
        x, w_ih, w_hh, b_ih, b_hh, fc1_w, fc1_b, fc2_w, fc2_b, out);
}

// round 3
// speedup vs baseline: 1.1796x; 1.1103x over previous
#include <cuda_runtime.h>
#include <cstdint>

#define BATCH   32768
#define PAIRS   (BATCH / 2)      // 16384
#define TSTEPS  60
#define FIN     26
#define HID     24
#define G3      (3 * HID)        // 72
#define RPH     (HID / 2)        // 12 rows per half-thread
#define WSTRIDE 26               // padded u64 stride for both weight arrays

typedef unsigned long long u64;

// ---------- packed f32x2 helpers ----------
__device__ __forceinline__ u64 pk(float a, float b) {
    u64 r;
    asm("mov.b64 %0, {%1, %2};" : "=l"(r) : "f"(a), "f"(b));
    return r;
}
__device__ __forceinline__ void upk(u64 v, float& a, float& b) {
    asm("mov.b64 {%0, %1}, %2;" : "=f"(a), "=f"(b) : "l"(v));
}
__device__ __forceinline__ void ffma2_ip(u64& acc, u64 a, u64 b) {
    asm("fma.rn.f32x2 %0, %1, %2, %0;" : "+l"(acc) : "l"(a), "l"(b));
}

// ---------- fast activations (≈1e-6 rel err) ----------
__device__ __forceinline__ float sigmoidf_(float x) {
    return __fdividef(1.0f, 1.0f + __expf(-x));
}
__device__ __forceinline__ float tanhf_(float x) {
    float s = __fdividef(2.0f, 1.0f + __expf(-2.0f * x));
    return s - 1.0f;
}

__global__ void __launch_bounds__(224, 1)
_ShotRNN_90417651516362_kernel(
    const float* __restrict__ x,      // [B, T, 26]
    const float* __restrict__ w_ih,   // [72, 26]
    const float* __restrict__ w_hh,   // [72, 24]
    const float* __restrict__ b_ih,   // [72]
    const float* __restrict__ b_hh,   // [72]
    const float* __restrict__ fc1_w,  // [8, 24]
    const float* __restrict__ fc1_b,  // [8]
    const float* __restrict__ fc2_w,  // [4, 8]
    const float* __restrict__ fc2_b,  // [4]
    float* __restrict__ out)          // [B, 4]
{
    // Duplicated-pair (w,w) weights; both arrays padded to stride 26 u64 so
    // the two cooperating halves (rows r and r+12) hit different banks:
    // 12*26*8 = 2496 B -> +16 banks. 26*8 = 208 B keeps 16B alignment.
    __shared__ __align__(16) u64 s_wih[G3 * WSTRIDE];
    __shared__ __align__(16) u64 s_whh[G3 * WSTRIDE];
    __shared__ __align__(16) u64 s_br[HID];
    __shared__ __align__(16) u64 s_bz[HID];
    __shared__ __align__(16) u64 s_bnx[HID];
    __shared__ __align__(16) u64 s_bnh[HID];
    __shared__ __align__(16) u64 s_f1w[8 * HID];
    __shared__ __align__(16) u64 s_f1b[8];
    __shared__ __align__(16) u64 s_f2w[4 * 8];
    __shared__ __align__(16) u64 s_f2b[4];

    const int tid = threadIdx.x;
    const int blk = blockDim.x;

    for (int i = tid; i < G3 * FIN; i += blk) {
        int r = i / FIN, c = i % FIN;
        float w = w_ih[i];
        s_wih[r * WSTRIDE + c] = pk(w, w);
    }
    for (int i = tid; i < G3 * HID; i += blk) {
        int r = i / HID, c = i % HID;
        float w = w_hh[i];
        s_whh[r * WSTRIDE + c] = pk(w, w);
    }
    for (int i = tid; i < HID; i += blk) {
        float br = b_ih[i]         + b_hh[i];         s_br[i]  = pk(br, br);
        float bz = b_ih[HID + i]   + b_hh[HID + i];   s_bz[i]  = pk(bz, bz);
        float bx = b_ih[2*HID + i];                   s_bnx[i] = pk(bx, bx);
        float bh = b_hh[2*HID + i];                   s_bnh[i] = pk(bh, bh);
    }
    for (int i = tid; i < 8 * HID; i += blk) { float w = fc1_w[i]; s_f1w[i] = pk(w, w); }
    for (int i = tid; i < 8; i += blk)       { float w = fc1_b[i]; s_f1b[i] = pk(w, w); }
    for (int i = tid; i < 32; i += blk)      { float w = fc2_w[i]; s_f2w[i] = pk(w, w); }
    for (int i = tid; i < 4; i += blk)       { float w = fc2_b[i]; s_f2b[i] = pk(w, w); }
    __syncthreads();

    // Worker mapping: two consecutive threads (same warp, lanes 2k/2k+1)
    // cooperate on one batch-pair. Warp-aligned activity boundary.
    const int worker = blockIdx.x * blk + tid;
    const int pair = worker >> 1;
    const int half = worker & 1;
    if (pair >= PAIRS) return;

    const int base  = half * RPH;       // my gate rows:   base .. base+11
    const int obase = RPH - base;       // partner's rows: obase .. obase+11

    const float* xr0 = x + (size_t)(2 * pair) * (TSTEPS * FIN);
    const float* xr1 = xr0 + (TSTEPS * FIN);

    u64 h[HID];
#pragma unroll
    for (int i = 0; i < HID; i++) h[i] = 0ull;

#pragma unroll 1
    for (int t = 0; t < TSTEPS; t++) {
        // Both halves load the full x rows for the pair (DRAM is ~3% busy).
        float2 v0[FIN / 2], v1[FIN / 2];
        const float2* p0 = (const float2*)(xr0 + t * FIN);
        const float2* p1 = (const float2*)(xr1 + t * FIN);
#pragma unroll
        for (int f = 0; f < FIN / 2; f++) {
            v0[f] = __ldg(p0 + f);
            v1[f] = __ldg(p1 + f);
        }
        u64 xp[FIN];
#pragma unroll
        for (int f = 0; f < FIN / 2; f++) {
            xp[2*f]   = pk(v0[f].x, v1[f].x);
            xp[2*f+1] = pk(v0[f].y, v1[f].y);
        }

        u64 hn[RPH];
#pragma unroll 2
        for (int i = 0; i < RPH; i++) {
            const int r = base + i;
            u64 ar  = s_br[r];
            u64 az  = s_bz[r];
            u64 anx = s_bnx[r];
            u64 anh = s_bnh[r];

            // h-part first (SMEM-only; overlaps the x LDGs)
            const ulonglong2* ur = (const ulonglong2*)&s_whh[r * WSTRIDE];
            const ulonglong2* uz = (const ulonglong2*)&s_whh[(HID + r) * WSTRIDE];
            const ulonglong2* un = (const ulonglong2*)&s_whh[(2 * HID + r) * WSTRIDE];
#pragma unroll
            for (int j = 0; j < HID / 2; j++) {
                ulonglong2 a = ur[j], b = uz[j], c = un[j];
                ffma2_ip(ar,  h[2*j],   a.x);
                ffma2_ip(az,  h[2*j],   b.x);
                ffma2_ip(anh, h[2*j],   c.x);
                ffma2_ip(ar,  h[2*j+1], a.y);
                ffma2_ip(az,  h[2*j+1], b.y);
                ffma2_ip(anh, h[2*j+1], c.y);
            }

            // x-part
            const ulonglong2* wr = (const ulonglong2*)&s_wih[r * WSTRIDE];
            const ulonglong2* wz = (const ulonglong2*)&s_wih[(HID + r) * WSTRIDE];
            const ulonglong2* wn = (const ulonglong2*)&s_wih[(2 * HID + r) * WSTRIDE];
#pragma unroll
            for (int f = 0; f < FIN / 2; f++) {
                ulonglong2 a = wr[f], b = wz[f], c = wn[f];
                ffma2_ip(ar,  xp[2*f],   a.x);
                ffma2_ip(az,  xp[2*f],   b.x);
                ffma2_ip(anx, xp[2*f],   c.x);
                ffma2_ip(ar,  xp[2*f+1], a.y);
                ffma2_ip(az,  xp[2*f+1], b.y);
                ffma2_ip(anx, xp[2*f+1], c.y);
            }

            float arx, ary, azx, azy, nxx, nxy, nhx, nhy, h0, h1v;
            upk(ar, arx, ary);
            upk(az, azx, azy);
            upk(anx, nxx, nxy);
            upk(anh, nhx, nhy);
            upk(h[r], h0, h1v);

            float r0 = sigmoidf_(arx), r1 = sigmoidf_(ary);
            float z0 = sigmoidf_(azx), z1 = sigmoidf_(azy);
            float n0 = tanhf_(fmaf(r0, nhx, nxx));
            float n1 = tanhf_(fmaf(r1, nhy, nxy));
            float o0 = fmaf(z0, h0 - n0, n0);
            float o1 = fmaf(z1, h1v - n1, n1);
            hn[i] = pk(o0, o1);
        }

        // Exchange new-h halves with the partner lane (lane^1, same warp).
#pragma unroll
        for (int i = 0; i < RPH; i++) {
            u64 oth = __shfl_xor_sync(0xffffffffu, hn[i], 1);
            h[base + i]  = hn[i];
            h[obase + i] = oth;
        }
    }

    // FC head: trivial work, half 0 computes both packed batch elements.
    if (half != 0) return;

    u64 h1[8];
#pragma unroll
    for (int j = 0; j < 8; j++) {
        u64 acc = s_f1b[j];
        const ulonglong2* w = (const ulonglong2*)&s_f1w[j * HID];
#pragma unroll
        for (int k = 0; k < HID / 2; k++) {
            ulonglong2 a = w[k];
            ffma2_ip(acc, h[2*k],   a.x);
            ffma2_ip(acc, h[2*k+1], a.y);
        }
        float a, b;
        upk(acc, a, b);
        h1[j] = pk(fmaxf(a, 0.0f), fmaxf(b, 0.0f));
    }

    float l0[4], l1[4];
#pragma unroll
    for (int c = 0; c < 4; c++) {
        u64 acc = s_f2b[c];
        const ulonglong2* w = (const ulonglong2*)&s_f2w[c * 8];
#pragma unroll
        for (int k = 0; k < 4; k++) {
            ulonglong2 a = w[k];
            ffma2_ip(acc, h1[2*k],   a.x);
            ffma2_ip(acc, h1[2*k+1], a.y);
        }
        upk(acc, l0[c], l1[c]);
    }

    float* o0p = out + (size_t)(2 * pair) * 4;
    float* o1p = o0p + 4;
    {
        float m = fmaxf(fmaxf(l0[0], l0[1]), fmaxf(l0[2], l0[3]));
        float e[4]; float s = 0.0f;
#pragma unroll
        for (int c = 0; c < 4; c++) { e[c] = __expf(l0[c] - m); s += e[c]; }
        float inv = __fdividef(1.0f, s);
#pragma unroll
        for (int c = 0; c < 4; c++) o0p[c] = e[c] * inv;
    }
    {
        float m = fmaxf(fmaxf(l1[0], l1[1]), fmaxf(l1[2], l1[3]));
        float e[4]; float s = 0.0f;
#pragma unroll
        for (int c = 0; c < 4; c++) { e[c] = __expf(l1[c] - m); s += e[c]; }
        float inv = __fdividef(1.0f, s);
#pragma unroll
        for (int c = 0; c < 4; c++) o1p[c] = e[c] * inv;
    }
}

extern "C" void kernel_launch(void* const* d_in, const int* in_sizes, int n_in,
                              void* d_out, int out_size) {
    const float* x     = (const float*)d_in[0];
    const float* w_ih  = (const float*)d_in[1];
    const float* w_hh  = (const float*)d_in[2];
    const float* b_ih  = (const float*)d_in[3];
    const float* b_hh  = (const float*)d_in[4];
    const float* fc1_w = (const float*)d_in[5];
    const float* fc1_b = (const float*)d_in[6];
    const float* fc2_w = (const float*)d_in[7];
    const float* fc2_b = (const float*)d_in[8];
    float* out = (float*)d_out;

    // 148 CTAs x 224 threads = 33152 threads; 32768 active (warp-aligned tail).
    // 2 threads per batch-pair (gate-split), 7 busy warps on every SM.
    dim3 grid(148), block(224);
    _ShotRNN_90417651516362_kernel<<<grid, block>>>(
        x, w_ih, w_hh, b_ih, b_hh, fc1_w, fc1_b, fc2_w, fc2_b, out);
}